// round 6
// baseline (speedup 1.0000x reference)
#include <cuda_runtime.h>
#include <math.h>

#define BB 256
#define TT 512
#define NN 128
#define GO_IDX 1
#define EOS_IDX 2
#define NEGV -10000.0f
#define NSM 152

// __device__ global scratch (allowed; no dynamic allocation)
__device__ float  g_alpha[BB * TT * NN];  // entering alpha rows, bit-exact
__device__ float  g_mv[BB * TT * NN];     // pre-unary max rows
__device__ float2 g_mls[BB * TT];         // per-row {max, log-sum-exp}
__device__ int    g_assign[BB];           // LPT bid->batch
__device__ int    g_len[BB];
__device__ int    g_btag[BB];

// ---------------- kernel A: per-row softmax stats (float4 loads) ----------------
__global__ __launch_bounds__(256)
void softmax_pre(const float* __restrict__ unaries)
{
    int r = blockIdx.x * 8 + (threadIdx.x >> 5);   // row = b*TT + t
    int lane = threadIdx.x & 31;
    const float4* u = (const float4*)(unaries + (size_t)r * NN);
    float4 x = u[lane];
    float m = fmaxf(fmaxf(x.x, x.y), fmaxf(x.z, x.w));
    #pragma unroll
    for (int o = 16; o > 0; o >>= 1) m = fmaxf(m, __shfl_xor_sync(0xffffffffu, m, o));
    float e = expf(x.x - m) + expf(x.y - m) + expf(x.z - m) + expf(x.w - m);
    #pragma unroll
    for (int o = 16; o > 0; o >>= 1) e += __shfl_xor_sync(0xffffffffu, e, o);
    if (lane == 0) g_mls[r] = make_float2(m, logf(e));
}

// ---------------- kernel B: lengths + LPT pairing ----------------
__global__ __launch_bounds__(256)
void prep_assign(const void* __restrict__ lengths_raw)
{
    __shared__ long long key[BB];
    int tid = threadIdx.x;
    const int* li = (const int*)lengths_raw;
    int len = (li[1] == 0) ? (int)(((const long long*)lengths_raw)[tid]) : li[tid];
    len = max(1, min(TT, len));
    g_len[tid] = len;
    key[tid] = ((long long)len << 32) | (long long)tid;
    __syncthreads();
    for (int k = 2; k <= BB; k <<= 1) {
        for (int jj = k >> 1; jj > 0; jj >>= 1) {
            int ixj = tid ^ jj;
            if (ixj > tid) {
                long long a = key[tid], c = key[ixj];
                bool desc = ((tid & k) == 0);
                if (desc ? (a < c) : (a > c)) { key[tid] = c; key[ixj] = a; }
            }
            __syncthreads();
        }
    }
    int rank = (tid < NSM) ? tid : (NSM + BB - 1 - tid);
    rank = min(BB - 1, max(0, rank));
    g_assign[tid] = (int)(key[rank] & 0xffffffffLL);
}

// ---------------- kernel C: max-only forward ----------------
// smem: ts 64KB | mls 4KB | bufA 512 | bufB 512 | termv 512
#define FW_SMEM (65536 + 4096 + 512 + 512 + 512)

__global__ __launch_bounds__(256, 2)
void viterbi_fwd(const float* __restrict__ unaries,
                 const float* __restrict__ trans,
                 float* __restrict__ out)
{
    extern __shared__ unsigned char sm[];
    float*  ts    = (float*)sm;                       // NN*NN
    float2* mlsS  = (float2*)(sm + 65536);            // TT
    float*  bufA  = (float*)(sm + 65536 + 4096);      // NN
    float*  bufB  = bufA + NN;                        // NN
    float*  termv = bufB + NN;                        // NN

    int b = g_assign[blockIdx.x];
    b = min(BB - 1, max(0, b));
    const int tid = threadIdx.x;
    const int j = tid >> 1;       // cur tag
    const int h = tid & 1;        // half: chunks 2k+h
    const int len = g_len[b];

    for (int idx = tid; idx < NN * NN; idx += 256) ts[idx] = trans[idx];
    for (int idx = tid; idx < TT; idx += 256) mlsS[idx] = g_mls[b * TT + idx];
    if (h == 0) bufA[j] = (j == GO_IDX) ? 0.0f : NEGV;   // exact log_softmax identity
    __syncthreads();

    float tr[64];
    #pragma unroll
    for (int k = 0; k < 16; ++k) {
        float4 v = *(const float4*)(ts + j * NN + (2 * k + h) * 4);
        tr[4*k+0] = v.x; tr[4*k+1] = v.y; tr[4*k+2] = v.z; tr[4*k+3] = v.w;
    }

    const float* ub = unaries + (size_t)b * TT * NN;
    const float BIG = -3.402823466e38f;
    float pa = (j == GO_IDX) ? 0.0f : NEGV;   // entering alpha[j]
    float ucur = ub[j];
    float* rd = bufA;
    float* wr = bufB;

    for (int t = 0; t < len; ++t) {
        float unext = (t + 1 < len) ? ub[(t + 1) * NN + j] : 0.0f;

        float mvv[8];
        #pragma unroll
        for (int c = 0; c < 8; ++c) mvv[c] = BIG;
        #pragma unroll
        for (int k = 0; k < 16; ++k) {
            float4 a4 = ((const float4*)rd)[2 * k + h];   // even/odd chunks: disjoint banks
            float v0 = a4.x + tr[4*k+0];
            float v1 = a4.y + tr[4*k+1];
            float v2 = a4.z + tr[4*k+2];
            float v3 = a4.w + tr[4*k+3];
            mvv[k >> 1] = fmaxf(mvv[k >> 1], fmaxf(fmaxf(v0, v1), fmaxf(v2, v3)));
        }
        float bv = fmaxf(fmaxf(fmaxf(mvv[0], mvv[1]), fmaxf(mvv[2], mvv[3])),
                         fmaxf(fmaxf(mvv[4], mvv[5]), fmaxf(mvv[6], mvv[7])));
        bv = fmaxf(bv, __shfl_xor_sync(0xffffffffu, bv, 1));  // cross-half combine

        float2 c2 = mlsS[t];
        float na = bv + ((ucur - c2.x) - c2.y);   // normalized probv, round-1 op order

        size_t rowo = ((size_t)b * TT + t) * NN + j;
        if (h == 0) { wr[j] = na; g_alpha[rowo] = pa; }
        else        { g_mv[rowo] = bv; }

        pa = na; ucur = unext;
        float* tmp = rd; rd = wr; wr = tmp;
        __syncthreads();   // single barrier: double-buffered alpha
    }

    // terminal: entering alpha = pa (all threads hold it)
    float term = pa + ts[EOS_IDX * NN + j];
    if (h == 0) termv[j] = term;
    __syncthreads();
    if (tid == 0) {
        float bvv = termv[0]; int bi = 0;
        #pragma unroll 4
        for (int p = 1; p < NN; ++p)
            if (termv[p] > bvv) { bvv = termv[p]; bi = p; }   // strict > : first index
        out[(size_t)BB * TT + b] = bvv;
        g_btag[b] = bi;
    }
}

// ---------------- kernel D: backtrace via equality match ----------------
#define BT_SMEM 65536

__global__ __launch_bounds__(256, 1)
void viterbi_bt(const float* __restrict__ trans, float* __restrict__ out)
{
    extern __shared__ float ts[];   // NN*NN
    const int tid = threadIdx.x;
    for (int idx = tid; idx < NN * NN; idx += 256) ts[idx] = trans[idx];
    __syncthreads();

    const int wid = tid >> 5, lane = tid & 31;
    const int b = blockIdx.x * 8 + wid;
    const int len = g_len[b];
    int cur = g_btag[b];
    float* po = out + (size_t)b * TT;

    // zero tail (t >= len)
    for (int t = len + lane; t < TT; t += 32) po[t] = 0.0f;

    const float4* Ab = (const float4*)(g_alpha + (size_t)b * TT * NN);
    const float4* Mb = (const float4*)(g_mv    + (size_t)b * TT * NN);

    int t = len - 1;
    // 3-deep prefetch pipeline (rows clamped to >=0; unused slots harmless)
    float4 A0, M0, A1, M1, A2, M2;
    {
        int r0 = max(t, 0), r1 = max(t - 1, 0), r2 = max(t - 2, 0);
        A0 = Ab[(size_t)r0 * 32 + lane]; M0 = Mb[(size_t)r0 * 32 + lane];
        A1 = Ab[(size_t)r1 * 32 + lane]; M1 = Mb[(size_t)r1 * 32 + lane];
        A2 = Ab[(size_t)r2 * 32 + lane]; M2 = Mb[(size_t)r2 * 32 + lane];
    }

#define BT_STEP(AA, MM)                                                     \
    {                                                                        \
        if (lane == 0) po[t] = (float)cur;                                   \
        float t01 = (cur & 1) ? MM.y : MM.x;                                 \
        float t23 = (cur & 1) ? MM.w : MM.z;                                 \
        float tgt = (cur & 2) ? t23 : t01;                                   \
        tgt = __shfl_sync(0xffffffffu, tgt, cur >> 2);                       \
        float4 trow = *(const float4*)(ts + cur * NN + lane * 4);            \
        unsigned lp = 0xffffffffu;                                           \
        if (AA.w + trow.w == tgt) lp = 4u * lane + 3u;                       \
        if (AA.z + trow.z == tgt) lp = 4u * lane + 2u;                       \
        if (AA.y + trow.y == tgt) lp = 4u * lane + 1u;                       \
        if (AA.x + trow.x == tgt) lp = 4u * lane + 0u;                       \
        cur = (int)(__reduce_min_sync(0xffffffffu, lp) & 127u);              \
        int rl = max(t - 3, 0);                                              \
        AA = Ab[(size_t)rl * 32 + lane]; MM = Mb[(size_t)rl * 32 + lane];    \
        --t;                                                                 \
    }

    while (t >= 1) {
        BT_STEP(A0, M0);
        if (t < 1) break;
        BT_STEP(A1, M1);
        if (t < 1) break;
        BT_STEP(A2, M2);
    }
    if (lane == 0) po[0] = (float)cur;
#undef BT_STEP
}

extern "C" void kernel_launch(void* const* d_in, const int* in_sizes, int n_in,
                              void* d_out, int out_size)
{
    const float* unaries = (const float*)d_in[0];
    const float* trans   = (const float*)d_in[1];
    const void*  lengths = d_in[2];
    float* out = (float*)d_out;

    prep_assign<<<1, 256>>>(lengths);
    softmax_pre<<<BB * TT / 8, 256>>>(unaries);
    cudaFuncSetAttribute(viterbi_fwd,
                         cudaFuncAttributeMaxDynamicSharedMemorySize, FW_SMEM);
    viterbi_fwd<<<BB, 256, FW_SMEM>>>(unaries, trans, out);
    cudaFuncSetAttribute(viterbi_bt,
                         cudaFuncAttributeMaxDynamicSharedMemorySize, BT_SMEM);
    viterbi_bt<<<BB / 8, 256, BT_SMEM>>>(trans, out);
}

// round 7
// speedup vs baseline: 1.1507x; 1.1507x over previous
#include <cuda_runtime.h>
#include <math.h>

#define BB 256
#define TT 512
#define NN 128
#define GO_IDX 1
#define EOS_IDX 2
#define NEGV -10000.0f
#define NSM 152

__device__ float2 g_mls[BB * TT];   // per (b,t): {max, log-sum-exp}
__device__ int    g_assign[BB];     // LPT bid->batch
__device__ int    g_len[BB];

// ---------------- kernel A: per-row softmax stats (float4 loads) ----------------
__global__ __launch_bounds__(256)
void softmax_pre(const float* __restrict__ unaries)
{
    int r = blockIdx.x * 8 + (threadIdx.x >> 5);   // row = b*TT + t
    int lane = threadIdx.x & 31;
    const float4* u = (const float4*)(unaries + (size_t)r * NN);
    float4 x = u[lane];
    float m = fmaxf(fmaxf(x.x, x.y), fmaxf(x.z, x.w));
    #pragma unroll
    for (int o = 16; o > 0; o >>= 1) m = fmaxf(m, __shfl_xor_sync(0xffffffffu, m, o));
    float e = expf(x.x - m) + expf(x.y - m) + expf(x.z - m) + expf(x.w - m);
    #pragma unroll
    for (int o = 16; o > 0; o >>= 1) e += __shfl_xor_sync(0xffffffffu, e, o);
    if (lane == 0) g_mls[r] = make_float2(m, logf(e));
}

// ---------------- kernel B: lengths + LPT pairing ----------------
__global__ __launch_bounds__(256)
void prep_assign(const void* __restrict__ lengths_raw)
{
    __shared__ long long key[BB];
    int tid = threadIdx.x;
    const int* li = (const int*)lengths_raw;
    int len = (li[1] == 0) ? (int)(((const long long*)lengths_raw)[tid]) : li[tid];
    len = max(1, min(TT, len));
    g_len[tid] = len;
    key[tid] = ((long long)len << 32) | (long long)tid;
    __syncthreads();
    for (int k = 2; k <= BB; k <<= 1) {
        for (int jj = k >> 1; jj > 0; jj >>= 1) {
            int ixj = tid ^ jj;
            if (ixj > tid) {
                long long a = key[tid], c = key[ixj];
                bool desc = ((tid & k) == 0);
                if (desc ? (a < c) : (a > c)) { key[tid] = c; key[ixj] = a; }
            }
            __syncthreads();
        }
    }
    int rank = (tid < NSM) ? tid : (NSM + BB - 1 - tid);
    rank = min(BB - 1, max(0, rank));
    g_assign[tid] = (int)(key[rank] & 0xffffffffLL);
}

// ---------------- kernel C: integrated Viterbi DP, 512 threads ----------------
// smem: bp 65536 (trans staging first) | alpha 512 | partv 2048 | parti 2048 | mls 4096
#define SMEM_BYTES (65536 + 512 + 2048 + 2048 + 4096)

__global__ __launch_bounds__(512, 2)
void viterbi5(const float* __restrict__ unaries,
              const float* __restrict__ trans,
              float* __restrict__ out)
{
    extern __shared__ unsigned char smem[];
    unsigned char* bp = smem;                       // TT*NN (trans staging first)
    float*  alpha = (float*)(smem + 65536);         // NN
    float*  partv = alpha + NN;                     // 4*NN
    int*    parti = (int*)(partv + 4 * NN);         // 4*NN
    float2* mlsS  = (float2*)(parti + 4 * NN);      // TT

    int b = g_assign[blockIdx.x];
    b = min(BB - 1, max(0, b));
    const int tid = threadIdx.x;
    const int j   = tid & (NN - 1);     // cur tag
    const int q   = tid >> 7;           // prev quarter (0..3)
    const int len = g_len[b];

    // stage trans coalesced -> regs; load softmax stats
    float* ts = (float*)bp;
    for (int idx = tid; idx < NN * NN; idx += 512) ts[idx] = trans[idx];
    for (int idx = tid; idx < TT; idx += 512) mlsS[idx] = g_mls[b * TT + idx];
    if (tid < NN) alpha[tid] = (tid == GO_IDX) ? 0.0f : NEGV;  // exact log_softmax identity
    __syncthreads();

    float tr[32];
    {
        const float4* base = (const float4*)(ts + j * NN + (q << 5));
        #pragma unroll
        for (int k = 0; k < 8; ++k) {
            float4 v = base[k];
            tr[4*k+0] = v.x; tr[4*k+1] = v.y; tr[4*k+2] = v.z; tr[4*k+3] = v.w;
        }
    }
    __syncthreads();   // done reading ts before bp overwrites it

    const float* ub = unaries + (size_t)b * TT * NN;
    const float4* ap4 = (const float4*)(alpha + (q << 5));
    const float BIG = -3.402823466e38f;

    float ucur = (tid < NN) ? ub[j] : 0.0f;

    for (int t = 0; t < len; ++t) {
        float unext = 0.0f;
        if (tid < NN && t + 1 < len) unext = ub[(t + 1) * NN + j];  // prefetch

        // 4 independent argmax chains over blocks of 8 prev (local idx 0..31)
        float mv[4]; int mi[4];
        #pragma unroll
        for (int c = 0; c < 4; ++c) { mv[c] = BIG; mi[c] = c * 8; }
        #pragma unroll
        for (int k = 0; k < 8; ++k) {
            float4 a4 = ap4[k];                    // broadcast LDS.128
            const int c = k >> 1;
            const int p = k * 4;
            float v0 = a4.x + tr[p+0];
            float v1 = a4.y + tr[p+1];
            float v2 = a4.z + tr[p+2];
            float v3 = a4.w + tr[p+3];
            if (v0 > mv[c]) { mv[c] = v0; mi[c] = p+0; }
            if (v1 > mv[c]) { mv[c] = v1; mi[c] = p+1; }
            if (v2 > mv[c]) { mv[c] = v2; mi[c] = p+2; }
            if (v3 > mv[c]) { mv[c] = v3; mi[c] = p+3; }
        }
        float bv = mv[0]; int bi = mi[0];
        #pragma unroll
        for (int c = 1; c < 4; ++c)
            if (mv[c] > bv) { bv = mv[c]; bi = mi[c]; }   // strict > : first index

        partv[(q << 7) + j] = bv;
        parti[(q << 7) + j] = bi + (q << 5);
        __syncthreads();

        if (tid < NN) {
            // combine quarters in index order; strict > keeps lowest prev on ties
            float m = partv[j]; int i_ = parti[j];
            #pragma unroll
            for (int c = 1; c < 4; ++c) {
                float v = partv[(c << 7) + j];
                if (v > m) { m = v; i_ = parti[(c << 7) + j]; }
            }
            bp[t * NN + j] = (unsigned char)i_;
            float2 c2 = mlsS[t];
            alpha[j] = m + ((ucur - c2.x) - c2.y);        // normalized probv
        }
        ucur = unext;
        __syncthreads();
    }

    // terminal + backtrace (reuse partv row 0)
    if (tid < NN) partv[tid] = alpha[tid] + trans[EOS_IDX * NN + tid];
    __syncthreads();

    if (tid == 0) {
        float bv = partv[0]; int bi = 0;
        #pragma unroll 4
        for (int p = 1; p < NN; ++p)
            if (partv[p] > bv) { bv = partv[p]; bi = p; }
        out[(size_t)BB * TT + b] = bv;
        int cur = bi;
        float* po = out + (size_t)b * TT;
        for (int t = len - 1; t >= 0; --t) {
            po[t] = (float)cur;
            if (t > 0) cur = bp[t * NN + cur];
        }
    }
    for (int t = len + tid; t < TT; t += 512)
        out[(size_t)b * TT + t] = 0.0f;
}

extern "C" void kernel_launch(void* const* d_in, const int* in_sizes, int n_in,
                              void* d_out, int out_size)
{
    const float* unaries = (const float*)d_in[0];
    const float* trans   = (const float*)d_in[1];
    const void*  lengths = d_in[2];
    float* out = (float*)d_out;

    prep_assign<<<1, 256>>>(lengths);
    softmax_pre<<<BB * TT / 8, 256>>>(unaries);
    cudaFuncSetAttribute(viterbi5,
                         cudaFuncAttributeMaxDynamicSharedMemorySize, SMEM_BYTES);
    viterbi5<<<BB, 512, SMEM_BYTES>>>(unaries, trans, out);
}